// round 5
// baseline (speedup 1.0000x reference)
#include <cuda_runtime.h>

#define CHK   64            // chunk size (power of two)
#define CHKB  6             // log2(CHK)
#define WUP   128           // warm-up steps
#define TOT   (WUP + CHK)   // 192 serial iterations per worker
#define NMAX  20000

__device__ float g_c[NMAX];   // c0 per step, natural order
__device__ float g_obsstd;

struct P {
    const float *x, *y, *pm, *ps;
    const int   *lag;
    const float *wr_yom, *wr_yom_fp, *wr_yom_gw, *wr_ylm, *wr_yfm;
    const float *wb1_yom, *wb1_gw, *wb1_fp, *wb2_ylm, *theltaC;
    const float *b0_yom, *b0_gw, *b0_fp, *b0_ylm;
    float *out;
    int N;
};

__device__ __forceinline__ float ex2f(float x) {
    float y; asm("ex2.approx.ftz.f32 %0, %1;" : "=f"(y) : "f"(x)); return y;
}
__device__ __forceinline__ float rcpf(float x) {
    float y; asm("rcp.approx.ftz.f32 %0, %1;" : "=f"(y) : "f"(x)); return y;
}

struct Consts {
    float expC, mo, so;
    float Ao, Bo, ko;     // yom gate:  gate = rcp(fma(ex2(Ao+Bo*c), k, k))
    float Agw, Bgw, kgw;
    float Afp, Bfp, kfp;
    float Aol, Bol, kol;  // ylm gate over u2
};

__device__ __forceinline__ Consts mkc(const P& p) {
    Consts c;
    float e1 = __expf(p.wr_yom[0]);
    float e2 = __expf(p.wr_yom_gw[0]);
    float e3 = __expf(p.wr_ylm[0]);
    float e4 = __expf(p.wr_yfm[0]);
    float e5 = __expf(p.wr_yom_fp[0]);
    float inv_d = 1.0f / (e1 + e2 + e3 + e4 + e5);
    c.expC = __expf(p.theltaC[0]);
    c.mo = p.pm[0]; c.so = p.ps[0];
    const float L2E = 1.4426950408889634f;
    const float ML = 2.9086f, SL = 1.898f;
    float is = 1.0f / c.so;
    float w;
    w = p.wb1_yom[0]; c.Bo  = -L2E * w * is; c.Ao  = L2E * (w * c.mo * is - p.b0_yom[0]); c.ko  = 1.0f / (e1 * inv_d);
    w = p.wb1_gw[0];  c.Bgw = -L2E * w * is; c.Agw = L2E * (w * c.mo * is - p.b0_gw[0]);  c.kgw = 1.0f / (e2 * inv_d);
    w = p.wb1_fp[0];  c.Bfp = -L2E * w * is; c.Afp = L2E * (w * c.mo * is - p.b0_fp[0]);  c.kfp = 1.0f / (e5 * inv_d);
    w = p.wb2_ylm[0]; c.Bol = -L2E * w / SL; c.Aol = L2E * (w * ML / SL - p.b0_ylm[0]);   c.kol = 1.0f / (e3 * inv_d);
    return c;
}

__device__ __forceinline__ float gatef(float v, float A, float B, float k) {
    float e = ex2f(fmaf(B, v, A));
    return rcpf(fmaf(e, k, k));
}

struct Pre { float a, u1, u2, ol; };   // a = u1 - expC

__device__ __forceinline__ Pre mkpre(float u1, float u2, const Consts& k) {
    Pre r;
    r.a  = u1 - k.expC;
    r.u1 = u1; r.u2 = u2;
    r.ol = gatef(u2, k.Aol, k.Bol, k.kol);
    return r;
}

// load steps b, b+1 (b even) from x; zeros outside [0, N)
__device__ __forceinline__ float4 fetch(const float* x, int b, int N) {
    if (b >= 0 && b + 1 < N)
        return *(const float4*)(x + 2 * b);
    float4 z = make_float4(0.f, 0.f, 0.f, 0.f);
    if (b >= 0 && b < N) { z.x = x[2 * b]; z.y = x[2 * b + 1]; }
    return z;
}

// ---- kernel 1: fused chunked scan (+ obsstd in the extra block) ----
__global__ void __launch_bounds__(32, 1) k_scan(P p) {
    int nchunks = (p.N + CHK - 1) >> CHKB;
    int scanb = (nchunks + 31) >> 5;

    if ((int)blockIdx.x == scanb) {
        // obsstd = std(y[365:15000], ddof=1); 32 threads, 4 chains each
        int tid = threadIdx.x;
        double s[4] = {0, 0, 0, 0}, q[4] = {0, 0, 0, 0};
        int cnt = 0;
        #pragma unroll 4
        for (int i = 365 + tid; i < 15000; i += 32, cnt++) {
            double v = (double)p.y[i];
            s[cnt & 3] += v; q[cnt & 3] += v * v;
        }
        double S = (s[0] + s[1]) + (s[2] + s[3]);
        double Q = (q[0] + q[1]) + (q[2] + q[3]);
        for (int o = 16; o > 0; o >>= 1) {
            S += __shfl_down_sync(0xffffffffu, S, o);
            Q += __shfl_down_sync(0xffffffffu, Q, o);
        }
        if (tid == 0) {
            double n = 14635.0;
            double mu = S / n;
            g_obsstd = (float)sqrt((Q - n * mu * mu) / (n - 1.0));
        }
        return;
    }

    int w = blockIdx.x * 32 + threadIdx.x;   // worker = chunk id
    if (w >= nchunks) return;
    Consts k = mkc(p);
    int lag = p.lag[0];
    int N = p.N;
    int base = (w << CHKB) - WUP;            // even -> float4-aligned
    const float* x = p.x;

    float c = 0.0f;

    Pre A0, A1, A2, A3;
    {
        float4 X = fetch(x, base + 0, N);
        float4 Y = fetch(x, base + 2, N);
        A0 = mkpre(X.x, X.y, k); A1 = mkpre(X.z, X.w, k);
        A2 = mkpre(Y.x, Y.y, k); A3 = mkpre(Y.z, Y.w, k);
    }

#define STEP(PR, J)                                                   \
    {                                                                 \
        int   bg = base + (J);                                        \
        float c0 = c;                                                 \
        float px = fmaxf(c0 + (PR).a, 0.0f);                          \
        float tt = c0 + ((PR).u1 - px);                               \
        float go  = gatef(c0, k.Ao,  k.Bo,  k.ko);                    \
        float ggw = gatef(c0, k.Agw, k.Bgw, k.kgw);                   \
        float gfp = gatef(c0, k.Afp, k.Bfp, k.kfp);                   \
        float lc  = fminf((PR).ol * c0, (PR).u2);  /* olc*c0 exact */ \
        float s   = (go + gfp) + ggw;                                 \
        float cn  = fmaf(-s, c0, tt - lc);                            \
        if ((J) >= WUP && bg < N) g_c[bg] = c0;                       \
        c = (bg >= lag) ? cn : c0;                                    \
    }

    for (int j = 0; j < TOT; j += 4) {
        float4 X = fetch(x, base + j + 4, N);
        float4 Y = fetch(x, base + j + 6, N);
        Pre B0 = mkpre(X.x, X.y, k), B1 = mkpre(X.z, X.w, k);
        Pre B2 = mkpre(Y.x, Y.y, k), B3 = mkpre(Y.z, Y.w, k);
        STEP(A0, j + 0);
        STEP(A1, j + 1);
        STEP(A2, j + 2);
        STEP(A3, j + 3);
        A0 = B0; A1 = B1; A2 = B2; A3 = B3;
    }
#undef STEP
}

// ---- kernel 2: parallel epilogue — all 16 outputs ----
__global__ void k_post(P p) {
    int b = blockIdx.x * blockDim.x + threadIdx.x;
    if (b >= p.N) return;
    Consts k = mkc(p);
    int lag = p.lag[0];

    float2 u = ((const float2*)p.x)[b];
    float u1 = u.x, u2 = u.y;
    float ol = gatef(u2, k.Aol, k.Bol, k.kol);
    float c0 = g_c[b];
    float m  = (b >= lag) ? 1.0f : 0.0f;

    float px = fmaxf(c0 + (u1 - k.expC), 0.0f);
    float ib = (u1 > 0.0f) ? px * rcpf(u1) : 0.0f;

    float go  = gatef(c0, k.Ao,  k.Bo,  k.ko);
    float ggw = gatef(c0, k.Agw, k.Bgw, k.kgw);
    float gfp = gatef(c0, k.Afp, k.Bfp, k.kfp);

    float v   = ol - fmaxf(ol - u2 * rcpf(c0), 0.0f);
    float olc = (c0 > 0.0f) ? v : ol;
    float f   = 1.0f - go - gfp - ggw - olc;
    float h   = fmaf(go, c0, px);
    float os  = g_obsstd * m;

    int N = p.N;
    float* o = p.out;
    o[0 * N + b]  = h * m;          // h
    o[1 * N + b]  = gfp * c0 * m;   // hfp
    o[2 * N + b]  = c0 * m;         // c
    o[3 * N + b]  = ol * c0 * m;    // l
    o[4 * N + b]  = olc * c0 * m;   // lc
    o[5 * N + b]  = px * m;         // bp
    o[6 * N + b]  = ggw * c0 * m;   // gw
    o[7 * N + b]  = ib * m;         // ib
    o[8 * N + b]  = go * m;         // oo
    o[9 * N + b]  = gfp * m;        // oofp
    o[10 * N + b] = ol * m;         // ol
    o[11 * N + b] = olc * m;        // olc
    o[12 * N + b] = f * m;          // f
    o[13 * N + b] = ggw * m;        // oogw
    float2* hn = (float2*)(o + 14 * N);   // h_nout: [N,2] = concat(h, obs_std)
    hn[b] = make_float2(h * m, os);
    o[16 * N + b] = os;             // obs_std
}

extern "C" void kernel_launch(void* const* d_in, const int* in_sizes, int n_in,
                              void* d_out, int out_size) {
    P p;
    p.x        = (const float*)d_in[0];
    p.y        = (const float*)d_in[1];
    p.pm       = (const float*)d_in[2];
    p.ps       = (const float*)d_in[3];
    // d_in[4] = epoch (unused)
    p.lag      = (const int*)d_in[5];
    p.wr_yom    = (const float*)d_in[6];
    p.wr_yom_fp = (const float*)d_in[7];
    p.wr_yom_gw = (const float*)d_in[8];
    p.wr_ylm    = (const float*)d_in[9];
    p.wr_yfm    = (const float*)d_in[10];
    p.wb1_yom   = (const float*)d_in[11];
    p.wb1_gw    = (const float*)d_in[12];
    p.wb1_fp    = (const float*)d_in[13];
    p.wb2_ylm   = (const float*)d_in[14];
    p.theltaC   = (const float*)d_in[15];
    p.b0_yom    = (const float*)d_in[16];
    p.b0_gw     = (const float*)d_in[17];
    p.b0_fp     = (const float*)d_in[18];
    p.b0_ylm    = (const float*)d_in[19];
    p.out = (float*)d_out;
    p.N = in_sizes[0] / 2;

    int nchunks = (p.N + CHK - 1) / CHK;          // 313
    int scan_blocks = (nchunks + 31) / 32;        // 10
    k_scan<<<scan_blocks + 1, 32>>>(p);           // +1 block for obsstd
    k_post<<<(p.N + 255) / 256, 256>>>(p);
}